// round 11
// baseline (speedup 1.0000x reference)
#include <cuda_runtime.h>
#include <cuda_bf16.h>
#include <cuda_fp16.h>
#include <cstdint>

// Problem constants (fixed by the dataset)
#define NNODES 50000
#define NFEAT  256
#define NHID   64
#define HOPS   4
#define NEDGES 800000
#define OUTC   (HOPS * NHID)          // 256
#define NSEG   (NNODES * HOPS)        // 200000 segments (divisible by 4)
#define TOTE   (HOPS * NEDGES)        // 3.2M edges

// Scratch buffers
__device__ __half g_h[(size_t)NNODES * OUTC];               // h (fp16) [node][hop*64+j]
__device__ __nv_bfloat16 g_x_hi[(size_t)NNODES * NFEAT];    // x bf16 hi
__device__ __nv_bfloat16 g_x_lo[(size_t)NNODES * NFEAT];    // x bf16 lo
__device__ __nv_bfloat16 g_Wt_hi[HOPS * NHID * NFEAT];      // [hop][n][k] bf16 hi
__device__ __nv_bfloat16 g_Wt_lo[HOPS * NHID * NFEAT];      // [hop][n][k] bf16 lo
__device__ int      g_counts[NSEG];
__device__ int      g_offsets[NSEG];
__device__ int      g_head[NSEG];
__device__ uint32_t g_packed[TOTE];     // (col:16) | (fp16 val bits:16)

#define SCAN_CHUNK 2048
#define NSCANBLK ((NSEG + SCAN_CHUNK - 1) / SCAN_CHUNK)     // 98
__device__ int g_blksum[NSCANBLK];
__device__ int g_blkoff[NSCANBLK];

__device__ __forceinline__ uint32_t smem_to_u32(const void* smem_ptr) {
    uint32_t addr;
    asm("{ .reg .u64 tmp; cvta.to.shared.u64 tmp, %1; cvt.u32.u64 %0, tmp; }"
        : "=r"(addr) : "l"(smem_ptr));
    return addr;
}

#define LDSM_X4(d, addr) \
    asm volatile("ldmatrix.sync.aligned.m8n8.x4.shared.b16 {%0,%1,%2,%3}, [%4];" \
                 : "=r"((d)[0]), "=r"((d)[1]), "=r"((d)[2]), "=r"((d)[3]) \
                 : "r"(addr))

__device__ __forceinline__ void mma_bf16(float* c, const uint32_t* a, const uint32_t* b)
{
    asm volatile(
        "mma.sync.aligned.m16n8k16.row.col.f32.bf16.bf16.f32 "
        "{%0,%1,%2,%3}, {%4,%5,%6,%7}, {%8,%9}, {%0,%1,%2,%3};"
        : "+f"(c[0]), "+f"(c[1]), "+f"(c[2]), "+f"(c[3])
        : "r"(a[0]), "r"(a[1]), "r"(a[2]), "r"(a[3]), "r"(b[0]), "r"(b[1]));
}

// cp.async 16B; src_size = 16 (copy) or 0 (zero-fill)
__device__ __forceinline__ void cp_async16(uint32_t dst, const void* src, uint32_t src_size)
{
    asm volatile("cp.async.cg.shared.global [%0], [%1], 16, %2;"
                 :: "r"(dst), "l"(src), "r"(src_size) : "memory");
}
#define CP_COMMIT() asm volatile("cp.async.commit_group;" ::: "memory")
#define CP_WAIT(n)  asm volatile("cp.async.wait_group %0;" :: "n"(n) : "memory")

// ---------------------------------------------------------------------------
// x convert: g_x_hi/lo = bf16_split(x)
// ---------------------------------------------------------------------------
__global__ void sign_xconv_kernel(const float* __restrict__ x)
{
    size_t i = ((size_t)blockIdx.x * blockDim.x + threadIdx.x) * 4;
    if (i >= (size_t)NNODES * NFEAT) return;
    float4 v = *(const float4*)(x + i);
    __nv_bfloat162 h0 = __floats2bfloat162_rn(v.x, v.y);
    __nv_bfloat162 h1 = __floats2bfloat162_rn(v.z, v.w);
    __nv_bfloat162 l0 = __floats2bfloat162_rn(v.x - __bfloat162float(h0.x),
                                              v.y - __bfloat162float(h0.y));
    __nv_bfloat162 l1 = __floats2bfloat162_rn(v.z - __bfloat162float(h1.x),
                                              v.w - __bfloat162float(h1.y));
    uint2 hv, lv;
    hv.x = *(uint32_t*)&h0; hv.y = *(uint32_t*)&h1;
    lv.x = *(uint32_t*)&l0; lv.y = *(uint32_t*)&l1;
    *(uint2*)(g_x_hi + i) = hv;
    *(uint2*)(g_x_lo + i) = lv;
}

// ---------------------------------------------------------------------------
// W convert+transpose FUSED with zero_counts.
// blocks [0, 256)   : g_Wt[hop][n][k] = bf16_split(W[hop][k][n])  (65536 elems)
// blocks [256, 1038): zero g_counts (200000 ints)
// ---------------------------------------------------------------------------
#define WCONV_ELEMS (HOPS * NHID * NFEAT)   // 65536
__global__ void sign_wconv_zero_kernel(const float* __restrict__ W)
{
    int gidx = blockIdx.x * blockDim.x + threadIdx.x;
    if (gidx < WCONV_ELEMS) {
        int idx = gidx;
        int hop = idx >> 14;
        int n   = (idx >> 8) & 63;
        int k   = idx & 255;
        float v = W[((size_t)hop * NFEAT + k) * NHID + n];
        __nv_bfloat16 hi = __float2bfloat16_rn(v);
        __nv_bfloat16 lo = __float2bfloat16_rn(v - __bfloat162float(hi));
        g_Wt_hi[idx] = hi;
        g_Wt_lo[idx] = lo;
    } else {
        int z = gidx - WCONV_ELEMS;
        if (z < NSEG) g_counts[z] = 0;
    }
}

// ---------------------------------------------------------------------------
// mma.sync GEMM, cp.async double-buffered. CTA = 128 rows x 128 cols (2 hops),
// bf16 hi/lo 3-term split (from pre-converted planes), fp16 output.
// Stage layout (64KB): [AHI 16K][ALO 16K][BHI 16K][BLO 16K], 2 stages.
// ---------------------------------------------------------------------------
#define ST_AHI 0
#define ST_ALO 16384
#define ST_BHI 32768
#define ST_BLO 49152
#define STAGE_SZ 65536
#define SM_TOTAL (2 * STAGE_SZ)
#define KCHUNK 64
#define NCHUNK (NFEAT / KCHUNK)   // 4

__global__ __launch_bounds__(256, 1) void sign_gemm_mma_kernel(
    const float* __restrict__ b,   // [HOPS*NHID]
    __half* __restrict__ h)        // [NNODES, OUTC] fp16
{
    extern __shared__ char smem[];
    const uint32_t sbase = smem_to_u32(smem);
    const int tid  = threadIdx.x;
    const int wid  = tid >> 5;
    const int lane = tid & 31;
    const int row0 = blockIdx.x * 128;
    const int cg   = blockIdx.y;

    const int m0 = (wid >> 1) * 32;
    const int n0 = (wid & 1) * 64;

    float acc[2][8][4];
    #pragma unroll
    for (int i = 0; i < 2; i++)
        #pragma unroll
        for (int j = 0; j < 8; j++)
            #pragma unroll
            for (int q = 0; q < 4; q++) acc[i][j][q] = 0.f;

    uint32_t aDst[4]; const __nv_bfloat16* aSrcHi[4]; const __nv_bfloat16* aSrcLo[4];
    uint32_t aSz[4];
    uint32_t bDst[4]; const __nv_bfloat16* bSrcHi[4]; const __nv_bfloat16* bSrcLo[4];
    #pragma unroll
    for (int p = 0; p < 4; p++) {
        int s = tid + p * 256;
        int r = s >> 3;
        int g = s & 7;
        uint32_t off = (uint32_t)(r * 128) + (uint32_t)((g << 4) ^ ((r & 7) << 4));
        int gm = row0 + r;
        aDst[p] = off;
        aSz[p]  = (gm < NNODES) ? 16u : 0u;
        size_t asrc = (size_t)(gm < NNODES ? gm : 0) * NFEAT + g * 8;
        aSrcHi[p] = g_x_hi + asrc;
        aSrcLo[p] = g_x_lo + asrc;
        bDst[p] = off;
        size_t bsrc = (size_t)(cg * 128 + r) * NFEAT + g * 8;
        bSrcHi[p] = g_Wt_hi + bsrc;
        bSrcLo[p] = g_Wt_lo + bsrc;
    }

    const int a_row = (lane & 7) + ((lane >> 3) & 1) * 8;
    const int a_sel = (lane >> 4) << 4;
    const int b_row = (lane & 7) + (lane >> 4) * 8;
    const int b_sel = ((lane >> 3) & 1) << 4;

    uint32_t aBase[2], aXor[2];
    #pragma unroll
    for (int mt = 0; mt < 2; mt++) {
        int r = m0 + mt * 16 + a_row;
        aBase[mt] = (uint32_t)(r * 128);
        aXor[mt]  = (uint32_t)(((r & 7) << 4) ^ a_sel);
    }
    uint32_t bBase[4], bXor[4];
    #pragma unroll
    for (int nt2 = 0; nt2 < 4; nt2++) {
        int r = n0 + nt2 * 16 + b_row;
        bBase[nt2] = (uint32_t)(r * 128);
        bXor[nt2]  = (uint32_t)(((r & 7) << 4) ^ b_sel);
    }

    // prefetch chunk 0 into stage 0
    {
        const uint32_t st = sbase;
        #pragma unroll
        for (int p = 0; p < 4; p++) {
            cp_async16(st + ST_AHI + aDst[p], aSrcHi[p], aSz[p]);
            cp_async16(st + ST_ALO + aDst[p], aSrcLo[p], aSz[p]);
            cp_async16(st + ST_BHI + bDst[p], bSrcHi[p], 16u);
            cp_async16(st + ST_BLO + bDst[p], bSrcLo[p], 16u);
        }
        CP_COMMIT();
    }

    for (int chunk = 0; chunk < NCHUNK; chunk++) {
        if (chunk + 1 < NCHUNK) {
            const uint32_t st = sbase + ((chunk + 1) & 1) * STAGE_SZ;
            const int koff = (chunk + 1) * KCHUNK;
            #pragma unroll
            for (int p = 0; p < 4; p++) {
                cp_async16(st + ST_AHI + aDst[p], aSrcHi[p] + koff, aSz[p]);
                cp_async16(st + ST_ALO + aDst[p], aSrcLo[p] + koff, aSz[p]);
                cp_async16(st + ST_BHI + bDst[p], bSrcHi[p] + koff, 16u);
                cp_async16(st + ST_BLO + bDst[p], bSrcLo[p] + koff, 16u);
            }
            CP_COMMIT();
            CP_WAIT(1);
        } else {
            CP_WAIT(0);
        }
        __syncthreads();

        const uint32_t st = sbase + (chunk & 1) * STAGE_SZ;
        #pragma unroll
        for (int ks = 0; ks < 4; ks++) {
            const uint32_t ks32 = ks * 32;
            uint32_t ah[2][4], al[2][4];
            #pragma unroll
            for (int mt = 0; mt < 2; mt++) {
                uint32_t col = ks32 ^ aXor[mt];
                LDSM_X4(ah[mt], st + ST_AHI + aBase[mt] + col);
                LDSM_X4(al[mt], st + ST_ALO + aBase[mt] + col);
            }
            #pragma unroll
            for (int nt2 = 0; nt2 < 4; nt2++) {
                uint32_t col = ks32 ^ bXor[nt2];
                uint32_t bh[4], bl[4];
                LDSM_X4(bh, st + ST_BHI + bBase[nt2] + col);
                LDSM_X4(bl, st + ST_BLO + bBase[nt2] + col);
                #pragma unroll
                for (int half = 0; half < 2; half++) {
                    int nt = nt2 * 2 + half;
                    #pragma unroll
                    for (int mt = 0; mt < 2; mt++) {
                        mma_bf16(acc[mt][nt], ah[mt], &bh[half * 2]);
                        mma_bf16(acc[mt][nt], ah[mt], &bl[half * 2]);
                        mma_bf16(acc[mt][nt], al[mt], &bh[half * 2]);
                    }
                }
            }
        }
        __syncthreads();
    }

    // epilogue: bias + fp16 store
    const int er = lane >> 2;
    const int ec = (lane & 3) * 2;
    #pragma unroll
    for (int mt = 0; mt < 2; mt++) {
        #pragma unroll
        for (int nt = 0; nt < 8; nt++) {
            int gm = row0 + m0 + mt * 16 + er;
            int gc = cg * 128 + n0 + nt * 8 + ec;
            float2 bias = *(const float2*)(b + gc);
            if (gm < NNODES) {
                __half2 o = __floats2half2_rn(acc[mt][nt][0] + bias.x,
                                              acc[mt][nt][1] + bias.y);
                *(__half2*)(h + (size_t)gm * OUTC + gc) = o;
            }
            if (gm + 8 < NNODES) {
                __half2 o = __floats2half2_rn(acc[mt][nt][2] + bias.x,
                                              acc[mt][nt][3] + bias.y);
                *(__half2*)(h + (size_t)(gm + 8) * OUTC + gc) = o;
            }
        }
    }
}

// ---------------------------------------------------------------------------
// Phase 1: histogram  seg = hop*NNODES + row
// ---------------------------------------------------------------------------
__global__ void sign_hist_kernel(const int* __restrict__ rows)
{
    int e   = blockIdx.x * blockDim.x + threadIdx.x;
    int hop = blockIdx.y;
    if (e >= NEDGES) return;
    int r = rows[hop * NEDGES + e];
    atomicAdd(&g_counts[hop * NNODES + r], 1);
}

// Phase 2a: per-block (2048-chunk) reduction of counts
__global__ __launch_bounds__(256) void sign_scan_reduce_kernel(void)
{
    __shared__ int ssum[256];
    int base = blockIdx.x * SCAN_CHUNK;
    int t = threadIdx.x;
    int s = 0;
    #pragma unroll
    for (int j = 0; j < 8; j++) {
        int idx = base + t * 8 + j;
        if (idx < NSEG) s += g_counts[idx];
    }
    ssum[t] = s;
    __syncthreads();
    for (int off = 128; off; off >>= 1) {
        if (t < off) ssum[t] += ssum[t + off];
        __syncthreads();
    }
    if (t == 0) g_blksum[blockIdx.x] = ssum[0];
}

// Phase 2b: exclusive scan of block sums (tiny, serial)
__global__ void sign_scan_blks_kernel(void)
{
    if (threadIdx.x == 0 && blockIdx.x == 0) {
        int acc = 0;
        for (int i = 0; i < NSCANBLK; i++) {
            int v = g_blksum[i];
            g_blkoff[i] = acc;
            acc += v;
        }
    }
}

// Phase 2c: final exclusive scan within each chunk; writes offsets + head
__global__ __launch_bounds__(256) void sign_scan_final_kernel(void)
{
    __shared__ int wsum[8];
    int base = blockIdx.x * SCAN_CHUNK;
    int t = threadIdx.x;
    int lane = t & 31, w = t >> 5;

    int v[8];
    int s = 0;
    #pragma unroll
    for (int j = 0; j < 8; j++) {
        int idx = base + t * 8 + j;
        v[j] = (idx < NSEG) ? g_counts[idx] : 0;
        s += v[j];
    }
    int incl = s;
    #pragma unroll
    for (int off = 1; off < 32; off <<= 1) {
        int n = __shfl_up_sync(0xFFFFFFFFu, incl, off);
        if (lane >= off) incl += n;
    }
    if (lane == 31) wsum[w] = incl;
    __syncthreads();
    if (w == 0 && lane < 8) {
        int ws = wsum[lane];
        int wincl = ws;
        #pragma unroll
        for (int off = 1; off < 8; off <<= 1) {
            int n = __shfl_up_sync(0xFFu, wincl, off);
            if (lane >= off) wincl += n;
        }
        wsum[lane] = wincl - ws;
    }
    __syncthreads();

    int run = (incl - s) + wsum[w] + g_blkoff[blockIdx.x];
    #pragma unroll
    for (int j = 0; j < 8; j++) {
        int idx = base + t * 8 + j;
        if (idx < NSEG) {
            g_offsets[idx] = run;
            g_head[idx]    = run;
        }
        run += v[j];
    }
}

// Phase 3: fill packed edge list: (col:16) | (fp16(val):16)  -- 4B per edge
__global__ void sign_fill_kernel(const int* __restrict__ rows,
                                 const int* __restrict__ cols,
                                 const float* __restrict__ vals)
{
    int e   = blockIdx.x * blockDim.x + threadIdx.x;
    int hop = blockIdx.y;
    if (e >= NEDGES) return;
    int idx = hop * NEDGES + e;
    int r = rows[idx];
    int pos = atomicAdd(&g_head[hop * NNODES + r], 1);
    uint32_t vbits = (uint32_t)__half_as_ushort(__float2half_rn(vals[idx]));
    g_packed[pos] = (uint32_t)cols[idx] | (vbits << 16);
}

// Phase 4: segment accumulate + ELU.
// TWO warps per segment (edges interleaved stride-2) -> per-warp serial
// gather chain halves, per-warp MLP stays low (R7 lesson). smem combine.
// 256 threads = 8 warps = 4 segments/block; NSEG % 4 == 0.
__global__ __launch_bounds__(256) void sign_accum_kernel(float* __restrict__ out)
{
    __shared__ float sacc[4][64];
    const int wid  = threadIdx.x >> 5;   // 0..7
    const int lane = threadIdx.x & 31;
    const int pair = wid >> 1;           // segment slot 0..3
    const int half = wid & 1;            // 0/1
    const int seg  = blockIdx.x * 4 + pair;

    const int hop = seg / NNODES;
    const int row = seg - hop * NNODES;
    const int start = g_offsets[seg];
    const int end   = (seg == NSEG - 1) ? TOTE : g_offsets[seg + 1];
    const int coloff = hop * NHID + lane * 2;

    const uint32_t* __restrict__ packed = g_packed;
    const __half*   __restrict__ hbuf   = g_h;

    float ax = 0.f, ay = 0.f;
    for (int i = start + half; i < end; i += 2) {
        uint32_t cv = packed[i];
        int c = (int)(cv & 0xFFFFu);
        float v = __half2float(__ushort_as_half((unsigned short)(cv >> 16)));
        __half2 hh = *(const __half2*)(hbuf + (size_t)c * OUTC + coloff);
        float2 f = __half22float2(hh);
        ax += v * f.x;
        ay += v * f.y;
    }

    if (half == 1) {
        sacc[pair][lane * 2]     = ax;
        sacc[pair][lane * 2 + 1] = ay;
    }
    __syncthreads();
    if (half == 0) {
        ax += sacc[pair][lane * 2];
        ay += sacc[pair][lane * 2 + 1];
        ax = (ax > 0.f) ? ax : expm1f(ax);
        ay = (ay > 0.f) ? ay : expm1f(ay);
        float2 o; o.x = ax; o.y = ay;
        *(float2*)(out + (size_t)row * OUTC + coloff) = o;
    }
}

// ---------------------------------------------------------------------------
extern "C" void kernel_launch(void* const* d_in, const int* in_sizes, int n_in,
                              void* d_out, int out_size)
{
    const float* x    = (const float*)d_in[0];
    const float* W    = (const float*)d_in[1];
    const float* b    = (const float*)d_in[2];
    const int*   rows = (const int*)  d_in[3];
    const int*   cols = (const int*)  d_in[4];
    const float* vals = (const float*)d_in[5];
    float* out = (float*)d_out;

    __half* h;
    cudaGetSymbolAddress((void**)&h, g_h);

    cudaFuncSetAttribute(sign_gemm_mma_kernel,
                         cudaFuncAttributeMaxDynamicSharedMemorySize, SM_TOTAL);

    // GEMM path (+ fused zero_counts)
    sign_xconv_kernel<<<(NNODES * NFEAT / 4 + 255) / 256, 256>>>(x);
    sign_wconv_zero_kernel<<<(WCONV_ELEMS + NSEG + 255) / 256, 256>>>(W);
    dim3 ggrid((NNODES + 127) / 128, 2);
    sign_gemm_mma_kernel<<<ggrid, 256, SM_TOTAL>>>(b, h);

    // Bucketing path
    dim3 egrid((NEDGES + 255) / 256, HOPS);
    sign_hist_kernel<<<egrid, 256>>>(rows);
    sign_scan_reduce_kernel<<<NSCANBLK, 256>>>();
    sign_scan_blks_kernel<<<1, 32>>>();
    sign_scan_final_kernel<<<NSCANBLK, 256>>>();
    sign_fill_kernel<<<egrid, 256>>>(rows, cols, vals);

    // Segment accumulate + ELU (2 warps/segment, writes every output element)
    sign_accum_kernel<<<NSEG / 4, 256>>>(out);
}

// round 12
// speedup vs baseline: 1.1538x; 1.1538x over previous
#include <cuda_runtime.h>
#include <cuda_bf16.h>
#include <cuda_fp16.h>
#include <cstdint>

// Problem constants (fixed by the dataset)
#define NNODES 50000
#define NFEAT  256
#define NHID   64
#define HOPS   4
#define NEDGES 800000
#define OUTC   (HOPS * NHID)          // 256
#define NSEG   (NNODES * HOPS)        // 200000 segments (even)
#define TOTE   (HOPS * NEDGES)        // 3.2M edges

// Scratch buffers
__device__ __half g_h[(size_t)NNODES * OUTC];               // h (fp16) [node][hop*64+j]
__device__ __nv_bfloat16 g_x_hi[(size_t)NNODES * NFEAT];    // x bf16 hi
__device__ __nv_bfloat16 g_x_lo[(size_t)NNODES * NFEAT];    // x bf16 lo
__device__ __nv_bfloat16 g_Wt_hi[HOPS * NHID * NFEAT];      // [hop][n][k] bf16 hi
__device__ __nv_bfloat16 g_Wt_lo[HOPS * NHID * NFEAT];      // [hop][n][k] bf16 lo
__device__ int   g_counts[NSEG];
__device__ int   g_offsets[NSEG];
__device__ int   g_head[NSEG];
__device__ uint2 g_sorted[TOTE];                            // packed (col, val_bits)

#define SCAN_CHUNK 2048
#define NSCANBLK ((NSEG + SCAN_CHUNK - 1) / SCAN_CHUNK)     // 98
__device__ int g_blksum[NSCANBLK];
__device__ int g_blkoff[NSCANBLK];

__device__ __forceinline__ uint32_t smem_to_u32(const void* smem_ptr) {
    uint32_t addr;
    asm("{ .reg .u64 tmp; cvta.to.shared.u64 tmp, %1; cvt.u32.u64 %0, tmp; }"
        : "=r"(addr) : "l"(smem_ptr));
    return addr;
}

#define LDSM_X4(d, addr) \
    asm volatile("ldmatrix.sync.aligned.m8n8.x4.shared.b16 {%0,%1,%2,%3}, [%4];" \
                 : "=r"((d)[0]), "=r"((d)[1]), "=r"((d)[2]), "=r"((d)[3]) \
                 : "r"(addr))

__device__ __forceinline__ void mma_bf16(float* c, const uint32_t* a, const uint32_t* b)
{
    asm volatile(
        "mma.sync.aligned.m16n8k16.row.col.f32.bf16.bf16.f32 "
        "{%0,%1,%2,%3}, {%4,%5,%6,%7}, {%8,%9}, {%0,%1,%2,%3};"
        : "+f"(c[0]), "+f"(c[1]), "+f"(c[2]), "+f"(c[3])
        : "r"(a[0]), "r"(a[1]), "r"(a[2]), "r"(a[3]), "r"(b[0]), "r"(b[1]));
}

// cp.async 16B; src_size = 16 (copy) or 0 (zero-fill)
__device__ __forceinline__ void cp_async16(uint32_t dst, const void* src, uint32_t src_size)
{
    asm volatile("cp.async.cg.shared.global [%0], [%1], 16, %2;"
                 :: "r"(dst), "l"(src), "r"(src_size) : "memory");
}
#define CP_COMMIT() asm volatile("cp.async.commit_group;" ::: "memory")
#define CP_WAIT(n)  asm volatile("cp.async.wait_group %0;" :: "n"(n) : "memory")

// ---------------------------------------------------------------------------
// x convert: g_x_hi/lo = bf16_split(x)
// ---------------------------------------------------------------------------
__global__ void sign_xconv_kernel(const float* __restrict__ x)
{
    size_t i = ((size_t)blockIdx.x * blockDim.x + threadIdx.x) * 4;
    if (i >= (size_t)NNODES * NFEAT) return;
    float4 v = *(const float4*)(x + i);
    __nv_bfloat162 h0 = __floats2bfloat162_rn(v.x, v.y);
    __nv_bfloat162 h1 = __floats2bfloat162_rn(v.z, v.w);
    __nv_bfloat162 l0 = __floats2bfloat162_rn(v.x - __bfloat162float(h0.x),
                                              v.y - __bfloat162float(h0.y));
    __nv_bfloat162 l1 = __floats2bfloat162_rn(v.z - __bfloat162float(h1.x),
                                              v.w - __bfloat162float(h1.y));
    uint2 hv, lv;
    hv.x = *(uint32_t*)&h0; hv.y = *(uint32_t*)&h1;
    lv.x = *(uint32_t*)&l0; lv.y = *(uint32_t*)&l1;
    *(uint2*)(g_x_hi + i) = hv;
    *(uint2*)(g_x_lo + i) = lv;
}

// ---------------------------------------------------------------------------
// W convert+transpose FUSED with zero_counts.
// ---------------------------------------------------------------------------
#define WCONV_ELEMS (HOPS * NHID * NFEAT)   // 65536
__global__ void sign_wconv_zero_kernel(const float* __restrict__ W)
{
    int gidx = blockIdx.x * blockDim.x + threadIdx.x;
    if (gidx < WCONV_ELEMS) {
        int idx = gidx;
        int hop = idx >> 14;
        int n   = (idx >> 8) & 63;
        int k   = idx & 255;
        float v = W[((size_t)hop * NFEAT + k) * NHID + n];
        __nv_bfloat16 hi = __float2bfloat16_rn(v);
        __nv_bfloat16 lo = __float2bfloat16_rn(v - __bfloat162float(hi));
        g_Wt_hi[idx] = hi;
        g_Wt_lo[idx] = lo;
    } else {
        int z = gidx - WCONV_ELEMS;
        if (z < NSEG) g_counts[z] = 0;
    }
}

// ---------------------------------------------------------------------------
// mma.sync GEMM, cp.async double-buffered. CTA = 128 rows x 128 cols (2 hops),
// bf16 hi/lo 3-term split (from pre-converted planes), fp16 output.
// Stage layout (64KB): [AHI 16K][ALO 16K][BHI 16K][BLO 16K], 2 stages.
// ---------------------------------------------------------------------------
#define ST_AHI 0
#define ST_ALO 16384
#define ST_BHI 32768
#define ST_BLO 49152
#define STAGE_SZ 65536
#define SM_TOTAL (2 * STAGE_SZ)
#define KCHUNK 64
#define NCHUNK (NFEAT / KCHUNK)   // 4

__global__ __launch_bounds__(256, 1) void sign_gemm_mma_kernel(
    const float* __restrict__ b,   // [HOPS*NHID]
    __half* __restrict__ h)        // [NNODES, OUTC] fp16
{
    extern __shared__ char smem[];
    const uint32_t sbase = smem_to_u32(smem);
    const int tid  = threadIdx.x;
    const int wid  = tid >> 5;
    const int lane = tid & 31;
    const int row0 = blockIdx.x * 128;
    const int cg   = blockIdx.y;

    const int m0 = (wid >> 1) * 32;
    const int n0 = (wid & 1) * 64;

    float acc[2][8][4];
    #pragma unroll
    for (int i = 0; i < 2; i++)
        #pragma unroll
        for (int j = 0; j < 8; j++)
            #pragma unroll
            for (int q = 0; q < 4; q++) acc[i][j][q] = 0.f;

    uint32_t aDst[4]; const __nv_bfloat16* aSrcHi[4]; const __nv_bfloat16* aSrcLo[4];
    uint32_t aSz[4];
    uint32_t bDst[4]; const __nv_bfloat16* bSrcHi[4]; const __nv_bfloat16* bSrcLo[4];
    #pragma unroll
    for (int p = 0; p < 4; p++) {
        int s = tid + p * 256;
        int r = s >> 3;
        int g = s & 7;
        uint32_t off = (uint32_t)(r * 128) + (uint32_t)((g << 4) ^ ((r & 7) << 4));
        int gm = row0 + r;
        aDst[p] = off;
        aSz[p]  = (gm < NNODES) ? 16u : 0u;
        size_t asrc = (size_t)(gm < NNODES ? gm : 0) * NFEAT + g * 8;
        aSrcHi[p] = g_x_hi + asrc;
        aSrcLo[p] = g_x_lo + asrc;
        bDst[p] = off;
        size_t bsrc = (size_t)(cg * 128 + r) * NFEAT + g * 8;
        bSrcHi[p] = g_Wt_hi + bsrc;
        bSrcLo[p] = g_Wt_lo + bsrc;
    }

    const int a_row = (lane & 7) + ((lane >> 3) & 1) * 8;
    const int a_sel = (lane >> 4) << 4;
    const int b_row = (lane & 7) + (lane >> 4) * 8;
    const int b_sel = ((lane >> 3) & 1) << 4;

    uint32_t aBase[2], aXor[2];
    #pragma unroll
    for (int mt = 0; mt < 2; mt++) {
        int r = m0 + mt * 16 + a_row;
        aBase[mt] = (uint32_t)(r * 128);
        aXor[mt]  = (uint32_t)(((r & 7) << 4) ^ a_sel);
    }
    uint32_t bBase[4], bXor[4];
    #pragma unroll
    for (int nt2 = 0; nt2 < 4; nt2++) {
        int r = n0 + nt2 * 16 + b_row;
        bBase[nt2] = (uint32_t)(r * 128);
        bXor[nt2]  = (uint32_t)(((r & 7) << 4) ^ b_sel);
    }

    // prefetch chunk 0 into stage 0
    {
        const uint32_t st = sbase;
        #pragma unroll
        for (int p = 0; p < 4; p++) {
            cp_async16(st + ST_AHI + aDst[p], aSrcHi[p], aSz[p]);
            cp_async16(st + ST_ALO + aDst[p], aSrcLo[p], aSz[p]);
            cp_async16(st + ST_BHI + bDst[p], bSrcHi[p], 16u);
            cp_async16(st + ST_BLO + bDst[p], bSrcLo[p], 16u);
        }
        CP_COMMIT();
    }

    for (int chunk = 0; chunk < NCHUNK; chunk++) {
        if (chunk + 1 < NCHUNK) {
            const uint32_t st = sbase + ((chunk + 1) & 1) * STAGE_SZ;
            const int koff = (chunk + 1) * KCHUNK;
            #pragma unroll
            for (int p = 0; p < 4; p++) {
                cp_async16(st + ST_AHI + aDst[p], aSrcHi[p] + koff, aSz[p]);
                cp_async16(st + ST_ALO + aDst[p], aSrcLo[p] + koff, aSz[p]);
                cp_async16(st + ST_BHI + bDst[p], bSrcHi[p] + koff, 16u);
                cp_async16(st + ST_BLO + bDst[p], bSrcLo[p] + koff, 16u);
            }
            CP_COMMIT();
            CP_WAIT(1);
        } else {
            CP_WAIT(0);
        }
        __syncthreads();

        const uint32_t st = sbase + (chunk & 1) * STAGE_SZ;
        #pragma unroll
        for (int ks = 0; ks < 4; ks++) {
            const uint32_t ks32 = ks * 32;
            uint32_t ah[2][4], al[2][4];
            #pragma unroll
            for (int mt = 0; mt < 2; mt++) {
                uint32_t col = ks32 ^ aXor[mt];
                LDSM_X4(ah[mt], st + ST_AHI + aBase[mt] + col);
                LDSM_X4(al[mt], st + ST_ALO + aBase[mt] + col);
            }
            #pragma unroll
            for (int nt2 = 0; nt2 < 4; nt2++) {
                uint32_t col = ks32 ^ bXor[nt2];
                uint32_t bh[4], bl[4];
                LDSM_X4(bh, st + ST_BHI + bBase[nt2] + col);
                LDSM_X4(bl, st + ST_BLO + bBase[nt2] + col);
                #pragma unroll
                for (int half = 0; half < 2; half++) {
                    int nt = nt2 * 2 + half;
                    #pragma unroll
                    for (int mt = 0; mt < 2; mt++) {
                        mma_bf16(acc[mt][nt], ah[mt], &bh[half * 2]);
                        mma_bf16(acc[mt][nt], ah[mt], &bl[half * 2]);
                        mma_bf16(acc[mt][nt], al[mt], &bh[half * 2]);
                    }
                }
            }
        }
        __syncthreads();
    }

    // epilogue: bias + fp16 store
    const int er = lane >> 2;
    const int ec = (lane & 3) * 2;
    #pragma unroll
    for (int mt = 0; mt < 2; mt++) {
        #pragma unroll
        for (int nt = 0; nt < 8; nt++) {
            int gm = row0 + m0 + mt * 16 + er;
            int gc = cg * 128 + n0 + nt * 8 + ec;
            float2 bias = *(const float2*)(b + gc);
            if (gm < NNODES) {
                __half2 o = __floats2half2_rn(acc[mt][nt][0] + bias.x,
                                              acc[mt][nt][1] + bias.y);
                *(__half2*)(h + (size_t)gm * OUTC + gc) = o;
            }
            if (gm + 8 < NNODES) {
                __half2 o = __floats2half2_rn(acc[mt][nt][2] + bias.x,
                                              acc[mt][nt][3] + bias.y);
                *(__half2*)(h + (size_t)(gm + 8) * OUTC + gc) = o;
            }
        }
    }
}

// ---------------------------------------------------------------------------
// Phase 1: histogram  seg = hop*NNODES + row
// ---------------------------------------------------------------------------
__global__ void sign_hist_kernel(const int* __restrict__ rows)
{
    int e   = blockIdx.x * blockDim.x + threadIdx.x;
    int hop = blockIdx.y;
    if (e >= NEDGES) return;
    int r = rows[hop * NEDGES + e];
    atomicAdd(&g_counts[hop * NNODES + r], 1);
}

// Phase 2a: per-block (2048-chunk) reduction of counts
__global__ __launch_bounds__(256) void sign_scan_reduce_kernel(void)
{
    __shared__ int ssum[256];
    int base = blockIdx.x * SCAN_CHUNK;
    int t = threadIdx.x;
    int s = 0;
    #pragma unroll
    for (int j = 0; j < 8; j++) {
        int idx = base + t * 8 + j;
        if (idx < NSEG) s += g_counts[idx];
    }
    ssum[t] = s;
    __syncthreads();
    for (int off = 128; off; off >>= 1) {
        if (t < off) ssum[t] += ssum[t + off];
        __syncthreads();
    }
    if (t == 0) g_blksum[blockIdx.x] = ssum[0];
}

// Phase 2b: exclusive scan of block sums (tiny, serial)
__global__ void sign_scan_blks_kernel(void)
{
    if (threadIdx.x == 0 && blockIdx.x == 0) {
        int acc = 0;
        for (int i = 0; i < NSCANBLK; i++) {
            int v = g_blksum[i];
            g_blkoff[i] = acc;
            acc += v;
        }
    }
}

// Phase 2c: final exclusive scan within each chunk; writes offsets + head
__global__ __launch_bounds__(256) void sign_scan_final_kernel(void)
{
    __shared__ int wsum[8];
    int base = blockIdx.x * SCAN_CHUNK;
    int t = threadIdx.x;
    int lane = t & 31, w = t >> 5;

    int v[8];
    int s = 0;
    #pragma unroll
    for (int j = 0; j < 8; j++) {
        int idx = base + t * 8 + j;
        v[j] = (idx < NSEG) ? g_counts[idx] : 0;
        s += v[j];
    }
    int incl = s;
    #pragma unroll
    for (int off = 1; off < 32; off <<= 1) {
        int n = __shfl_up_sync(0xFFFFFFFFu, incl, off);
        if (lane >= off) incl += n;
    }
    if (lane == 31) wsum[w] = incl;
    __syncthreads();
    if (w == 0 && lane < 8) {
        int ws = wsum[lane];
        int wincl = ws;
        #pragma unroll
        for (int off = 1; off < 8; off <<= 1) {
            int n = __shfl_up_sync(0xFFu, wincl, off);
            if (lane >= off) wincl += n;
        }
        wsum[lane] = wincl - ws;
    }
    __syncthreads();

    int run = (incl - s) + wsum[w] + g_blkoff[blockIdx.x];
    #pragma unroll
    for (int j = 0; j < 8; j++) {
        int idx = base + t * 8 + j;
        if (idx < NSEG) {
            g_offsets[idx] = run;
            g_head[idx]    = run;
        }
        run += v[j];
    }
}

// Phase 3: fill sorted edge list (packed col + val bits)
__global__ void sign_fill_kernel(const int* __restrict__ rows,
                                 const int* __restrict__ cols,
                                 const float* __restrict__ vals)
{
    int e   = blockIdx.x * blockDim.x + threadIdx.x;
    int hop = blockIdx.y;
    if (e >= NEDGES) return;
    int idx = hop * NEDGES + e;
    int r = rows[idx];
    int pos = atomicAdd(&g_head[hop * NNODES + r], 1);
    g_sorted[pos] = make_uint2((uint32_t)cols[idx], __float_as_uint(vals[idx]));
}

// Phase 4: segment accumulate + ELU (R6/R10 loop form, unroll x2).
// 64-thread blocks: 2 warps = 2 independent segments per CTA. Small CTAs
// shrink the max-of-N straggler effect (segment lengths ~Poisson(16)) and
// give the scheduler finer granularity.
__global__ __launch_bounds__(64) void sign_accum_kernel(float* __restrict__ out)
{
    const int wid  = threadIdx.x >> 5;       // 0..1
    const int lane = threadIdx.x & 31;
    const int seg  = blockIdx.x * 2 + wid;
    if (seg >= NSEG) return;

    const int hop = seg / NNODES;
    const int row = seg - hop * NNODES;
    const int start = g_offsets[seg];
    const int end   = (seg == NSEG - 1) ? TOTE : g_offsets[seg + 1];
    const int coloff = hop * NHID + lane * 2;

    float ax = 0.f, ay = 0.f;
    int i = start;
    for (; i + 1 < end; i += 2) {
        uint2 cv0 = g_sorted[i];
        uint2 cv1 = g_sorted[i + 1];
        __half2 h0 = *(const __half2*)(g_h + (size_t)cv0.x * OUTC + coloff);
        __half2 h1 = *(const __half2*)(g_h + (size_t)cv1.x * OUTC + coloff);
        float v0 = __uint_as_float(cv0.y);
        float v1 = __uint_as_float(cv1.y);
        float2 f0 = __half22float2(h0);
        float2 f1 = __half22float2(h1);
        ax += v0 * f0.x; ay += v0 * f0.y;
        ax += v1 * f1.x; ay += v1 * f1.y;
    }
    if (i < end) {
        uint2 cv = g_sorted[i];
        __half2 hh = *(const __half2*)(g_h + (size_t)cv.x * OUTC + coloff);
        float v = __uint_as_float(cv.y);
        float2 f = __half22float2(hh);
        ax += v * f.x; ay += v * f.y;
    }

    ax = (ax > 0.f) ? ax : expm1f(ax);
    ay = (ay > 0.f) ? ay : expm1f(ay);
    float2 o; o.x = ax; o.y = ay;
    *(float2*)(out + (size_t)row * OUTC + coloff) = o;
}

// ---------------------------------------------------------------------------
extern "C" void kernel_launch(void* const* d_in, const int* in_sizes, int n_in,
                              void* d_out, int out_size)
{
    const float* x    = (const float*)d_in[0];
    const float* W    = (const float*)d_in[1];
    const float* b    = (const float*)d_in[2];
    const int*   rows = (const int*)  d_in[3];
    const int*   cols = (const int*)  d_in[4];
    const float* vals = (const float*)d_in[5];
    float* out = (float*)d_out;

    __half* h;
    cudaGetSymbolAddress((void**)&h, g_h);

    cudaFuncSetAttribute(sign_gemm_mma_kernel,
                         cudaFuncAttributeMaxDynamicSharedMemorySize, SM_TOTAL);

    // GEMM path (+ fused zero_counts)
    sign_xconv_kernel<<<(NNODES * NFEAT / 4 + 255) / 256, 256>>>(x);
    sign_wconv_zero_kernel<<<(WCONV_ELEMS + NSEG + 255) / 256, 256>>>(W);
    dim3 ggrid((NNODES + 127) / 128, 2);
    sign_gemm_mma_kernel<<<ggrid, 256, SM_TOTAL>>>(b, h);

    // Bucketing path
    dim3 egrid((NEDGES + 255) / 256, HOPS);
    sign_hist_kernel<<<egrid, 256>>>(rows);
    sign_scan_reduce_kernel<<<NSCANBLK, 256>>>();
    sign_scan_blks_kernel<<<1, 32>>>();
    sign_scan_final_kernel<<<NSCANBLK, 256>>>();
    sign_fill_kernel<<<egrid, 256>>>(rows, cols, vals);

    // Segment accumulate + ELU (2-warp CTAs vs straggler effect)
    sign_accum_kernel<<<(NSEG + 1) / 2, 64>>>(out);
}

// round 13
// speedup vs baseline: 1.1879x; 1.0296x over previous
#include <cuda_runtime.h>
#include <cuda_bf16.h>
#include <cuda_fp16.h>
#include <cstdint>

// Problem constants (fixed by the dataset)
#define NNODES 50000
#define NFEAT  256
#define NHID   64
#define HOPS   4
#define NEDGES 800000
#define OUTC   (HOPS * NHID)          // 256
#define NSEG   (NNODES * HOPS)        // 200000 segments
#define TOTE   (HOPS * NEDGES)        // 3.2M edges

// Scratch buffers
__device__ __half g_h[(size_t)NNODES * OUTC];               // h (fp16) [node][hop*64+j]
__device__ __nv_bfloat16 g_x_hi[(size_t)NNODES * NFEAT];    // x bf16 hi
__device__ __nv_bfloat16 g_x_lo[(size_t)NNODES * NFEAT];    // x bf16 lo
__device__ __nv_bfloat16 g_Wt_hi[HOPS * NHID * NFEAT];      // [hop][n][k] bf16 hi
__device__ __nv_bfloat16 g_Wt_lo[HOPS * NHID * NFEAT];      // [hop][n][k] bf16 lo
__device__ int   g_counts[NSEG];
__device__ int   g_offsets[NSEG];
__device__ int   g_head[NSEG];
__device__ uint2 g_sorted[TOTE];                            // packed (col, val_bits)

#define SCAN_CHUNK 2048
#define NSCANBLK ((NSEG + SCAN_CHUNK - 1) / SCAN_CHUNK)     // 98
__device__ int g_blksum[NSCANBLK];
__device__ int g_blkoff[NSCANBLK];

__device__ __forceinline__ uint32_t smem_to_u32(const void* smem_ptr) {
    uint32_t addr;
    asm("{ .reg .u64 tmp; cvta.to.shared.u64 tmp, %1; cvt.u32.u64 %0, tmp; }"
        : "=r"(addr) : "l"(smem_ptr));
    return addr;
}

#define LDSM_X4(d, addr) \
    asm volatile("ldmatrix.sync.aligned.m8n8.x4.shared.b16 {%0,%1,%2,%3}, [%4];" \
                 : "=r"((d)[0]), "=r"((d)[1]), "=r"((d)[2]), "=r"((d)[3]) \
                 : "r"(addr))

__device__ __forceinline__ void mma_bf16(float* c, const uint32_t* a, const uint32_t* b)
{
    asm volatile(
        "mma.sync.aligned.m16n8k16.row.col.f32.bf16.bf16.f32 "
        "{%0,%1,%2,%3}, {%4,%5,%6,%7}, {%8,%9}, {%0,%1,%2,%3};"
        : "+f"(c[0]), "+f"(c[1]), "+f"(c[2]), "+f"(c[3])
        : "r"(a[0]), "r"(a[1]), "r"(a[2]), "r"(a[3]), "r"(b[0]), "r"(b[1]));
}

// cp.async 16B; src_size = 16 (copy) or 0 (zero-fill)
__device__ __forceinline__ void cp_async16(uint32_t dst, const void* src, uint32_t src_size)
{
    asm volatile("cp.async.cg.shared.global [%0], [%1], 16, %2;"
                 :: "r"(dst), "l"(src), "r"(src_size) : "memory");
}
#define CP_COMMIT() asm volatile("cp.async.commit_group;" ::: "memory")
#define CP_WAIT(n)  asm volatile("cp.async.wait_group %0;" :: "n"(n) : "memory")

// ---------------------------------------------------------------------------
// x convert: g_x_hi/lo = bf16_split(x)
// ---------------------------------------------------------------------------
__global__ void sign_xconv_kernel(const float* __restrict__ x)
{
    size_t i = ((size_t)blockIdx.x * blockDim.x + threadIdx.x) * 4;
    if (i >= (size_t)NNODES * NFEAT) return;
    float4 v = *(const float4*)(x + i);
    __nv_bfloat162 h0 = __floats2bfloat162_rn(v.x, v.y);
    __nv_bfloat162 h1 = __floats2bfloat162_rn(v.z, v.w);
    __nv_bfloat162 l0 = __floats2bfloat162_rn(v.x - __bfloat162float(h0.x),
                                              v.y - __bfloat162float(h0.y));
    __nv_bfloat162 l1 = __floats2bfloat162_rn(v.z - __bfloat162float(h1.x),
                                              v.w - __bfloat162float(h1.y));
    uint2 hv, lv;
    hv.x = *(uint32_t*)&h0; hv.y = *(uint32_t*)&h1;
    lv.x = *(uint32_t*)&l0; lv.y = *(uint32_t*)&l1;
    *(uint2*)(g_x_hi + i) = hv;
    *(uint2*)(g_x_lo + i) = lv;
}

// ---------------------------------------------------------------------------
// W convert+transpose: g_Wt[hop][n][k] = bf16_split(W[hop][k][n])
// ---------------------------------------------------------------------------
#define WCONV_ELEMS (HOPS * NHID * NFEAT)   // 65536
__global__ void sign_wconv_kernel(const float* __restrict__ W)
{
    int idx = blockIdx.x * blockDim.x + threadIdx.x;
    if (idx >= WCONV_ELEMS) return;
    int hop = idx >> 14;
    int n   = (idx >> 8) & 63;
    int k   = idx & 255;
    float v = W[((size_t)hop * NFEAT + k) * NHID + n];
    __nv_bfloat16 hi = __float2bfloat16_rn(v);
    __nv_bfloat16 lo = __float2bfloat16_rn(v - __bfloat162float(hi));
    g_Wt_hi[idx] = hi;
    g_Wt_lo[idx] = lo;
}

// ---------------------------------------------------------------------------
// Zero segment counters (side-stream chain head).
// ---------------------------------------------------------------------------
__global__ void sign_zero_counts_kernel(void)
{
    int i = blockIdx.x * blockDim.x + threadIdx.x;
    if (i < NSEG) g_counts[i] = 0;
}

// ---------------------------------------------------------------------------
// mma.sync GEMM, cp.async double-buffered. CTA = 128 rows x 128 cols (2 hops),
// bf16 hi/lo 3-term split, fp16 output.
// ---------------------------------------------------------------------------
#define ST_AHI 0
#define ST_ALO 16384
#define ST_BHI 32768
#define ST_BLO 49152
#define STAGE_SZ 65536
#define SM_TOTAL (2 * STAGE_SZ)
#define KCHUNK 64
#define NCHUNK (NFEAT / KCHUNK)   // 4

__global__ __launch_bounds__(256, 1) void sign_gemm_mma_kernel(
    const float* __restrict__ b,   // [HOPS*NHID]
    __half* __restrict__ h)        // [NNODES, OUTC] fp16
{
    extern __shared__ char smem[];
    const uint32_t sbase = smem_to_u32(smem);
    const int tid  = threadIdx.x;
    const int wid  = tid >> 5;
    const int lane = tid & 31;
    const int row0 = blockIdx.x * 128;
    const int cg   = blockIdx.y;

    const int m0 = (wid >> 1) * 32;
    const int n0 = (wid & 1) * 64;

    float acc[2][8][4];
    #pragma unroll
    for (int i = 0; i < 2; i++)
        #pragma unroll
        for (int j = 0; j < 8; j++)
            #pragma unroll
            for (int q = 0; q < 4; q++) acc[i][j][q] = 0.f;

    uint32_t aDst[4]; const __nv_bfloat16* aSrcHi[4]; const __nv_bfloat16* aSrcLo[4];
    uint32_t aSz[4];
    uint32_t bDst[4]; const __nv_bfloat16* bSrcHi[4]; const __nv_bfloat16* bSrcLo[4];
    #pragma unroll
    for (int p = 0; p < 4; p++) {
        int s = tid + p * 256;
        int r = s >> 3;
        int g = s & 7;
        uint32_t off = (uint32_t)(r * 128) + (uint32_t)((g << 4) ^ ((r & 7) << 4));
        int gm = row0 + r;
        aDst[p] = off;
        aSz[p]  = (gm < NNODES) ? 16u : 0u;
        size_t asrc = (size_t)(gm < NNODES ? gm : 0) * NFEAT + g * 8;
        aSrcHi[p] = g_x_hi + asrc;
        aSrcLo[p] = g_x_lo + asrc;
        bDst[p] = off;
        size_t bsrc = (size_t)(cg * 128 + r) * NFEAT + g * 8;
        bSrcHi[p] = g_Wt_hi + bsrc;
        bSrcLo[p] = g_Wt_lo + bsrc;
    }

    const int a_row = (lane & 7) + ((lane >> 3) & 1) * 8;
    const int a_sel = (lane >> 4) << 4;
    const int b_row = (lane & 7) + (lane >> 4) * 8;
    const int b_sel = ((lane >> 3) & 1) << 4;

    uint32_t aBase[2], aXor[2];
    #pragma unroll
    for (int mt = 0; mt < 2; mt++) {
        int r = m0 + mt * 16 + a_row;
        aBase[mt] = (uint32_t)(r * 128);
        aXor[mt]  = (uint32_t)(((r & 7) << 4) ^ a_sel);
    }
    uint32_t bBase[4], bXor[4];
    #pragma unroll
    for (int nt2 = 0; nt2 < 4; nt2++) {
        int r = n0 + nt2 * 16 + b_row;
        bBase[nt2] = (uint32_t)(r * 128);
        bXor[nt2]  = (uint32_t)(((r & 7) << 4) ^ b_sel);
    }

    // prefetch chunk 0 into stage 0
    {
        const uint32_t st = sbase;
        #pragma unroll
        for (int p = 0; p < 4; p++) {
            cp_async16(st + ST_AHI + aDst[p], aSrcHi[p], aSz[p]);
            cp_async16(st + ST_ALO + aDst[p], aSrcLo[p], aSz[p]);
            cp_async16(st + ST_BHI + bDst[p], bSrcHi[p], 16u);
            cp_async16(st + ST_BLO + bDst[p], bSrcLo[p], 16u);
        }
        CP_COMMIT();
    }

    for (int chunk = 0; chunk < NCHUNK; chunk++) {
        if (chunk + 1 < NCHUNK) {
            const uint32_t st = sbase + ((chunk + 1) & 1) * STAGE_SZ;
            const int koff = (chunk + 1) * KCHUNK;
            #pragma unroll
            for (int p = 0; p < 4; p++) {
                cp_async16(st + ST_AHI + aDst[p], aSrcHi[p] + koff, aSz[p]);
                cp_async16(st + ST_ALO + aDst[p], aSrcLo[p] + koff, aSz[p]);
                cp_async16(st + ST_BHI + bDst[p], bSrcHi[p] + koff, 16u);
                cp_async16(st + ST_BLO + bDst[p], bSrcLo[p] + koff, 16u);
            }
            CP_COMMIT();
            CP_WAIT(1);
        } else {
            CP_WAIT(0);
        }
        __syncthreads();

        const uint32_t st = sbase + (chunk & 1) * STAGE_SZ;
        #pragma unroll
        for (int ks = 0; ks < 4; ks++) {
            const uint32_t ks32 = ks * 32;
            uint32_t ah[2][4], al[2][4];
            #pragma unroll
            for (int mt = 0; mt < 2; mt++) {
                uint32_t col = ks32 ^ aXor[mt];
                LDSM_X4(ah[mt], st + ST_AHI + aBase[mt] + col);
                LDSM_X4(al[mt], st + ST_ALO + aBase[mt] + col);
            }
            #pragma unroll
            for (int nt2 = 0; nt2 < 4; nt2++) {
                uint32_t col = ks32 ^ bXor[nt2];
                uint32_t bh[4], bl[4];
                LDSM_X4(bh, st + ST_BHI + bBase[nt2] + col);
                LDSM_X4(bl, st + ST_BLO + bBase[nt2] + col);
                #pragma unroll
                for (int half = 0; half < 2; half++) {
                    int nt = nt2 * 2 + half;
                    #pragma unroll
                    for (int mt = 0; mt < 2; mt++) {
                        mma_bf16(acc[mt][nt], ah[mt], &bh[half * 2]);
                        mma_bf16(acc[mt][nt], ah[mt], &bl[half * 2]);
                        mma_bf16(acc[mt][nt], al[mt], &bh[half * 2]);
                    }
                }
            }
        }
        __syncthreads();
    }

    // epilogue: bias + fp16 store
    const int er = lane >> 2;
    const int ec = (lane & 3) * 2;
    #pragma unroll
    for (int mt = 0; mt < 2; mt++) {
        #pragma unroll
        for (int nt = 0; nt < 8; nt++) {
            int gm = row0 + m0 + mt * 16 + er;
            int gc = cg * 128 + n0 + nt * 8 + ec;
            float2 bias = *(const float2*)(b + gc);
            if (gm < NNODES) {
                __half2 o = __floats2half2_rn(acc[mt][nt][0] + bias.x,
                                              acc[mt][nt][1] + bias.y);
                *(__half2*)(h + (size_t)gm * OUTC + gc) = o;
            }
            if (gm + 8 < NNODES) {
                __half2 o = __floats2half2_rn(acc[mt][nt][2] + bias.x,
                                              acc[mt][nt][3] + bias.y);
                *(__half2*)(h + (size_t)(gm + 8) * OUTC + gc) = o;
            }
        }
    }
}

// ---------------------------------------------------------------------------
// Phase 1: histogram  seg = hop*NNODES + row
// ---------------------------------------------------------------------------
__global__ void sign_hist_kernel(const int* __restrict__ rows)
{
    int e   = blockIdx.x * blockDim.x + threadIdx.x;
    int hop = blockIdx.y;
    if (e >= NEDGES) return;
    int r = rows[hop * NEDGES + e];
    atomicAdd(&g_counts[hop * NNODES + r], 1);
}

// Phase 2a: per-block (2048-chunk) reduction of counts
__global__ __launch_bounds__(256) void sign_scan_reduce_kernel(void)
{
    __shared__ int ssum[256];
    int base = blockIdx.x * SCAN_CHUNK;
    int t = threadIdx.x;
    int s = 0;
    #pragma unroll
    for (int j = 0; j < 8; j++) {
        int idx = base + t * 8 + j;
        if (idx < NSEG) s += g_counts[idx];
    }
    ssum[t] = s;
    __syncthreads();
    for (int off = 128; off; off >>= 1) {
        if (t < off) ssum[t] += ssum[t + off];
        __syncthreads();
    }
    if (t == 0) g_blksum[blockIdx.x] = ssum[0];
}

// Phase 2b: exclusive scan of block sums (tiny, serial)
__global__ void sign_scan_blks_kernel(void)
{
    if (threadIdx.x == 0 && blockIdx.x == 0) {
        int acc = 0;
        for (int i = 0; i < NSCANBLK; i++) {
            int v = g_blksum[i];
            g_blkoff[i] = acc;
            acc += v;
        }
    }
}

// Phase 2c: final exclusive scan within each chunk; writes offsets + head
__global__ __launch_bounds__(256) void sign_scan_final_kernel(void)
{
    __shared__ int wsum[8];
    int base = blockIdx.x * SCAN_CHUNK;
    int t = threadIdx.x;
    int lane = t & 31, w = t >> 5;

    int v[8];
    int s = 0;
    #pragma unroll
    for (int j = 0; j < 8; j++) {
        int idx = base + t * 8 + j;
        v[j] = (idx < NSEG) ? g_counts[idx] : 0;
        s += v[j];
    }
    int incl = s;
    #pragma unroll
    for (int off = 1; off < 32; off <<= 1) {
        int n = __shfl_up_sync(0xFFFFFFFFu, incl, off);
        if (lane >= off) incl += n;
    }
    if (lane == 31) wsum[w] = incl;
    __syncthreads();
    if (w == 0 && lane < 8) {
        int ws = wsum[lane];
        int wincl = ws;
        #pragma unroll
        for (int off = 1; off < 8; off <<= 1) {
            int n = __shfl_up_sync(0xFFu, wincl, off);
            if (lane >= off) wincl += n;
        }
        wsum[lane] = wincl - ws;
    }
    __syncthreads();

    int run = (incl - s) + wsum[w] + g_blkoff[blockIdx.x];
    #pragma unroll
    for (int j = 0; j < 8; j++) {
        int idx = base + t * 8 + j;
        if (idx < NSEG) {
            g_offsets[idx] = run;
            g_head[idx]    = run;
        }
        run += v[j];
    }
}

// Phase 3: fill sorted edge list (packed col + val bits)
__global__ void sign_fill_kernel(const int* __restrict__ rows,
                                 const int* __restrict__ cols,
                                 const float* __restrict__ vals)
{
    int e   = blockIdx.x * blockDim.x + threadIdx.x;
    int hop = blockIdx.y;
    if (e >= NEDGES) return;
    int idx = hop * NEDGES + e;
    int r = rows[idx];
    int pos = atomicAdd(&g_head[hop * NNODES + r], 1);
    g_sorted[pos] = make_uint2((uint32_t)cols[idx], __float_as_uint(vals[idx]));
}

// Phase 4: segment accumulate + ELU (R10 form: 256 threads, 8 segs/block).
__global__ __launch_bounds__(256) void sign_accum_kernel(float* __restrict__ out)
{
    const int wid  = threadIdx.x >> 5;
    const int lane = threadIdx.x & 31;
    const int seg  = blockIdx.x * 8 + wid;
    if (seg >= NSEG) return;

    const int hop = seg / NNODES;
    const int row = seg - hop * NNODES;
    const int start = g_offsets[seg];
    const int end   = (seg == NSEG - 1) ? TOTE : g_offsets[seg + 1];
    const int coloff = hop * NHID + lane * 2;

    float ax = 0.f, ay = 0.f;
    int i = start;
    for (; i + 1 < end; i += 2) {
        uint2 cv0 = g_sorted[i];
        uint2 cv1 = g_sorted[i + 1];
        __half2 h0 = *(const __half2*)(g_h + (size_t)cv0.x * OUTC + coloff);
        __half2 h1 = *(const __half2*)(g_h + (size_t)cv1.x * OUTC + coloff);
        float v0 = __uint_as_float(cv0.y);
        float v1 = __uint_as_float(cv1.y);
        float2 f0 = __half22float2(h0);
        float2 f1 = __half22float2(h1);
        ax += v0 * f0.x; ay += v0 * f0.y;
        ax += v1 * f1.x; ay += v1 * f1.y;
    }
    if (i < end) {
        uint2 cv = g_sorted[i];
        __half2 hh = *(const __half2*)(g_h + (size_t)cv.x * OUTC + coloff);
        float v = __uint_as_float(cv.y);
        float2 f = __half22float2(hh);
        ax += v * f.x; ay += v * f.y;
    }

    ax = (ax > 0.f) ? ax : expm1f(ax);
    ay = (ay > 0.f) ? ay : expm1f(ay);
    float2 o; o.x = ax; o.y = ay;
    *(float2*)(out + (size_t)row * OUTC + coloff) = o;
}

// ---------------------------------------------------------------------------
// Launcher: fork capture into two parallel branches.
//   main (stream 0):  xconv -> wconv -> gemm --------------+-> accum
//   side:             zero -> hist -> scans -> fill  ------+
// Stream/events created once on first (non-capture) call; every call issues
// the identical launch + event sequence, so the captured graph is stable.
// ---------------------------------------------------------------------------
extern "C" void kernel_launch(void* const* d_in, const int* in_sizes, int n_in,
                              void* d_out, int out_size)
{
    const float* x    = (const float*)d_in[0];
    const float* W    = (const float*)d_in[1];
    const float* b    = (const float*)d_in[2];
    const int*   rows = (const int*)  d_in[3];
    const int*   cols = (const int*)  d_in[4];
    const float* vals = (const float*)d_in[5];
    float* out = (float*)d_out;

    __half* h;
    cudaGetSymbolAddress((void**)&h, g_h);

    static cudaStream_t s_side = nullptr;
    static cudaEvent_t  s_fork = nullptr, s_join = nullptr;
    if (s_side == nullptr) {
        cudaStreamCreateWithFlags(&s_side, cudaStreamNonBlocking);
        cudaEventCreateWithFlags(&s_fork, cudaEventDisableTiming);
        cudaEventCreateWithFlags(&s_join, cudaEventDisableTiming);
        cudaFuncSetAttribute(sign_gemm_mma_kernel,
                             cudaFuncAttributeMaxDynamicSharedMemorySize, SM_TOTAL);
    }

    // fork
    cudaEventRecord(s_fork, 0);
    cudaStreamWaitEvent(s_side, s_fork, 0);

    // ---- side chain: bucketing prep (independent of GEMM) ----
    sign_zero_counts_kernel<<<(NSEG + 255) / 256, 256, 0, s_side>>>();
    dim3 egrid((NEDGES + 255) / 256, HOPS);
    sign_hist_kernel<<<egrid, 256, 0, s_side>>>(rows);
    sign_scan_reduce_kernel<<<NSCANBLK, 256, 0, s_side>>>();
    sign_scan_blks_kernel<<<1, 32, 0, s_side>>>();
    sign_scan_final_kernel<<<NSCANBLK, 256, 0, s_side>>>();
    sign_fill_kernel<<<egrid, 256, 0, s_side>>>(rows, cols, vals);
    cudaEventRecord(s_join, s_side);

    // ---- main chain: GEMM path ----
    sign_xconv_kernel<<<(NNODES * NFEAT / 4 + 255) / 256, 256>>>(x);
    sign_wconv_kernel<<<(WCONV_ELEMS + 255) / 256, 256>>>(W);
    dim3 ggrid((NNODES + 127) / 128, 2);
    sign_gemm_mma_kernel<<<ggrid, 256, SM_TOTAL>>>(b, h);

    // join, then accum (needs both g_h and g_sorted/g_offsets)
    cudaStreamWaitEvent(0, s_join, 0);
    sign_accum_kernel<<<(NSEG + 7) / 8, 256>>>(out);
}

// round 15
// speedup vs baseline: 1.1897x; 1.0015x over previous
#include <cuda_runtime.h>
#include <cuda_bf16.h>
#include <cuda_fp16.h>
#include <cstdint>

// Problem constants (fixed by the dataset)
#define NNODES 50000
#define NFEAT  256
#define NHID   64
#define HOPS   4
#define NEDGES 800000
#define OUTC   (HOPS * NHID)          // 256
#define NSEG   (NNODES * HOPS)        // 200000 segments
#define TOTE   (HOPS * NEDGES)        // 3.2M edges

// Scratch buffers
__device__ __half g_h[(size_t)NNODES * OUTC];               // h (fp16) [node][hop*64+j]
__device__ __nv_bfloat16 g_x_hi[(size_t)NNODES * NFEAT];    // x bf16 hi
__device__ __nv_bfloat16 g_x_lo[(size_t)NNODES * NFEAT];    // x bf16 lo
__device__ __nv_bfloat16 g_Wt_hi[HOPS * NHID * NFEAT];      // [hop][n][k] bf16 hi
__device__ __nv_bfloat16 g_Wt_lo[HOPS * NHID * NFEAT];      // [hop][n][k] bf16 lo
__device__ int   g_counts[NSEG];
__device__ int   g_offsets[NSEG];
__device__ int   g_head[NSEG];
__device__ uint2 g_sorted[TOTE];                            // packed (col, val_bits)

#define SCAN_CHUNK 2048
#define NSCANBLK ((NSEG + SCAN_CHUNK - 1) / SCAN_CHUNK)     // 98
__device__ int g_blksum[NSCANBLK];
__device__ int g_blkoff[NSCANBLK];

__device__ __forceinline__ uint32_t smem_to_u32(const void* smem_ptr) {
    uint32_t addr;
    asm("{ .reg .u64 tmp; cvta.to.shared.u64 tmp, %1; cvt.u32.u64 %0, tmp; }"
        : "=r"(addr) : "l"(smem_ptr));
    return addr;
}

#define LDSM_X4(d, addr) \
    asm volatile("ldmatrix.sync.aligned.m8n8.x4.shared.b16 {%0,%1,%2,%3}, [%4];" \
                 : "=r"((d)[0]), "=r"((d)[1]), "=r"((d)[2]), "=r"((d)[3]) \
                 : "r"(addr))

__device__ __forceinline__ void mma_bf16(float* c, const uint32_t* a, const uint32_t* b)
{
    asm volatile(
        "mma.sync.aligned.m16n8k16.row.col.f32.bf16.bf16.f32 "
        "{%0,%1,%2,%3}, {%4,%5,%6,%7}, {%8,%9}, {%0,%1,%2,%3};"
        : "+f"(c[0]), "+f"(c[1]), "+f"(c[2]), "+f"(c[3])
        : "r"(a[0]), "r"(a[1]), "r"(a[2]), "r"(a[3]), "r"(b[0]), "r"(b[1]));
}

// cp.async 16B; src_size = 16 (copy) or 0 (zero-fill)
__device__ __forceinline__ void cp_async16(uint32_t dst, const void* src, uint32_t src_size)
{
    asm volatile("cp.async.cg.shared.global [%0], [%1], 16, %2;"
                 :: "r"(dst), "l"(src), "r"(src_size) : "memory");
}
#define CP_COMMIT() asm volatile("cp.async.commit_group;" ::: "memory")
#define CP_WAIT(n)  asm volatile("cp.async.wait_group %0;" :: "n"(n) : "memory")

// ---------------------------------------------------------------------------
// x convert: g_x_hi/lo = bf16_split(x)
// ---------------------------------------------------------------------------
__global__ void sign_xconv_kernel(const float* __restrict__ x)
{
    size_t i = ((size_t)blockIdx.x * blockDim.x + threadIdx.x) * 4;
    if (i >= (size_t)NNODES * NFEAT) return;
    float4 v = *(const float4*)(x + i);
    __nv_bfloat162 h0 = __floats2bfloat162_rn(v.x, v.y);
    __nv_bfloat162 h1 = __floats2bfloat162_rn(v.z, v.w);
    __nv_bfloat162 l0 = __floats2bfloat162_rn(v.x - __bfloat162float(h0.x),
                                              v.y - __bfloat162float(h0.y));
    __nv_bfloat162 l1 = __floats2bfloat162_rn(v.z - __bfloat162float(h1.x),
                                              v.w - __bfloat162float(h1.y));
    uint2 hv, lv;
    hv.x = *(uint32_t*)&h0; hv.y = *(uint32_t*)&h1;
    lv.x = *(uint32_t*)&l0; lv.y = *(uint32_t*)&l1;
    *(uint2*)(g_x_hi + i) = hv;
    *(uint2*)(g_x_lo + i) = lv;
}

// ---------------------------------------------------------------------------
// W convert+transpose: g_Wt[hop][n][k] = bf16_split(W[hop][k][n])
// ---------------------------------------------------------------------------
#define WCONV_ELEMS (HOPS * NHID * NFEAT)   // 65536
__global__ void sign_wconv_kernel(const float* __restrict__ W)
{
    int idx = blockIdx.x * blockDim.x + threadIdx.x;
    if (idx >= WCONV_ELEMS) return;
    int hop = idx >> 14;
    int n   = (idx >> 8) & 63;
    int k   = idx & 255;
    float v = W[((size_t)hop * NFEAT + k) * NHID + n];
    __nv_bfloat16 hi = __float2bfloat16_rn(v);
    __nv_bfloat16 lo = __float2bfloat16_rn(v - __bfloat162float(hi));
    g_Wt_hi[idx] = hi;
    g_Wt_lo[idx] = lo;
}

// ---------------------------------------------------------------------------
// Zero segment counters (side-stream chain head).
// ---------------------------------------------------------------------------
__global__ void sign_zero_counts_kernel(void)
{
    int i = blockIdx.x * blockDim.x + threadIdx.x;
    if (i < NSEG) g_counts[i] = 0;
}

// ---------------------------------------------------------------------------
// mma.sync GEMM, cp.async double-buffered. CTA = 128 rows x 128 cols.
// cg (column group = 2 hops) is now a kernel ARG so the two halves can be
// launched separately and pipelined against accum.
// ---------------------------------------------------------------------------
#define ST_AHI 0
#define ST_ALO 16384
#define ST_BHI 32768
#define ST_BLO 49152
#define STAGE_SZ 65536
#define SM_TOTAL (2 * STAGE_SZ)
#define KCHUNK 64
#define NCHUNK (NFEAT / KCHUNK)   // 4

__global__ __launch_bounds__(256, 1) void sign_gemm_mma_kernel(
    const float* __restrict__ b,   // [HOPS*NHID]
    __half* __restrict__ h,        // [NNODES, OUTC] fp16
    int cg)                        // 0: cols 0-127 (hops 0,1)  1: cols 128-255
{
    extern __shared__ char smem[];
    const uint32_t sbase = smem_to_u32(smem);
    const int tid  = threadIdx.x;
    const int wid  = tid >> 5;
    const int lane = tid & 31;
    const int row0 = blockIdx.x * 128;

    const int m0 = (wid >> 1) * 32;
    const int n0 = (wid & 1) * 64;

    float acc[2][8][4];
    #pragma unroll
    for (int i = 0; i < 2; i++)
        #pragma unroll
        for (int j = 0; j < 8; j++)
            #pragma unroll
            for (int q = 0; q < 4; q++) acc[i][j][q] = 0.f;

    uint32_t aDst[4]; const __nv_bfloat16* aSrcHi[4]; const __nv_bfloat16* aSrcLo[4];
    uint32_t aSz[4];
    uint32_t bDst[4]; const __nv_bfloat16* bSrcHi[4]; const __nv_bfloat16* bSrcLo[4];
    #pragma unroll
    for (int p = 0; p < 4; p++) {
        int s = tid + p * 256;
        int r = s >> 3;
        int g = s & 7;
        uint32_t off = (uint32_t)(r * 128) + (uint32_t)((g << 4) ^ ((r & 7) << 4));
        int gm = row0 + r;
        aDst[p] = off;
        aSz[p]  = (gm < NNODES) ? 16u : 0u;
        size_t asrc = (size_t)(gm < NNODES ? gm : 0) * NFEAT + g * 8;
        aSrcHi[p] = g_x_hi + asrc;
        aSrcLo[p] = g_x_lo + asrc;
        bDst[p] = off;
        size_t bsrc = (size_t)(cg * 128 + r) * NFEAT + g * 8;
        bSrcHi[p] = g_Wt_hi + bsrc;
        bSrcLo[p] = g_Wt_lo + bsrc;
    }

    const int a_row = (lane & 7) + ((lane >> 3) & 1) * 8;
    const int a_sel = (lane >> 4) << 4;
    const int b_row = (lane & 7) + (lane >> 4) * 8;
    const int b_sel = ((lane >> 3) & 1) << 4;

    uint32_t aBase[2], aXor[2];
    #pragma unroll
    for (int mt = 0; mt < 2; mt++) {
        int r = m0 + mt * 16 + a_row;
        aBase[mt] = (uint32_t)(r * 128);
        aXor[mt]  = (uint32_t)(((r & 7) << 4) ^ a_sel);
    }
    uint32_t bBase[4], bXor[4];
    #pragma unroll
    for (int nt2 = 0; nt2 < 4; nt2++) {
        int r = n0 + nt2 * 16 + b_row;
        bBase[nt2] = (uint32_t)(r * 128);
        bXor[nt2]  = (uint32_t)(((r & 7) << 4) ^ b_sel);
    }

    // prefetch chunk 0 into stage 0
    {
        const uint32_t st = sbase;
        #pragma unroll
        for (int p = 0; p < 4; p++) {
            cp_async16(st + ST_AHI + aDst[p], aSrcHi[p], aSz[p]);
            cp_async16(st + ST_ALO + aDst[p], aSrcLo[p], aSz[p]);
            cp_async16(st + ST_BHI + bDst[p], bSrcHi[p], 16u);
            cp_async16(st + ST_BLO + bDst[p], bSrcLo[p], 16u);
        }
        CP_COMMIT();
    }

    for (int chunk = 0; chunk < NCHUNK; chunk++) {
        if (chunk + 1 < NCHUNK) {
            const uint32_t st = sbase + ((chunk + 1) & 1) * STAGE_SZ;
            const int koff = (chunk + 1) * KCHUNK;
            #pragma unroll
            for (int p = 0; p < 4; p++) {
                cp_async16(st + ST_AHI + aDst[p], aSrcHi[p] + koff, aSz[p]);
                cp_async16(st + ST_ALO + aDst[p], aSrcLo[p] + koff, aSz[p]);
                cp_async16(st + ST_BHI + bDst[p], bSrcHi[p] + koff, 16u);
                cp_async16(st + ST_BLO + bDst[p], bSrcLo[p] + koff, 16u);
            }
            CP_COMMIT();
            CP_WAIT(1);
        } else {
            CP_WAIT(0);
        }
        __syncthreads();

        const uint32_t st = sbase + (chunk & 1) * STAGE_SZ;
        #pragma unroll
        for (int ks = 0; ks < 4; ks++) {
            const uint32_t ks32 = ks * 32;
            uint32_t ah[2][4], al[2][4];
            #pragma unroll
            for (int mt = 0; mt < 2; mt++) {
                uint32_t col = ks32 ^ aXor[mt];
                LDSM_X4(ah[mt], st + ST_AHI + aBase[mt] + col);
                LDSM_X4(al[mt], st + ST_ALO + aBase[mt] + col);
            }
            #pragma unroll
            for (int nt2 = 0; nt2 < 4; nt2++) {
                uint32_t col = ks32 ^ bXor[nt2];
                uint32_t bh[4], bl[4];
                LDSM_X4(bh, st + ST_BHI + bBase[nt2] + col);
                LDSM_X4(bl, st + ST_BLO + bBase[nt2] + col);
                #pragma unroll
                for (int half = 0; half < 2; half++) {
                    int nt = nt2 * 2 + half;
                    #pragma unroll
                    for (int mt = 0; mt < 2; mt++) {
                        mma_bf16(acc[mt][nt], ah[mt], &bh[half * 2]);
                        mma_bf16(acc[mt][nt], ah[mt], &bl[half * 2]);
                        mma_bf16(acc[mt][nt], al[mt], &bh[half * 2]);
                    }
                }
            }
        }
        __syncthreads();
    }

    // epilogue: bias + fp16 store
    const int er = lane >> 2;
    const int ec = (lane & 3) * 2;
    #pragma unroll
    for (int mt = 0; mt < 2; mt++) {
        #pragma unroll
        for (int nt = 0; nt < 8; nt++) {
            int gm = row0 + m0 + mt * 16 + er;
            int gc = cg * 128 + n0 + nt * 8 + ec;
            float2 bias = *(const float2*)(b + gc);
            if (gm < NNODES) {
                __half2 o = __floats2half2_rn(acc[mt][nt][0] + bias.x,
                                              acc[mt][nt][1] + bias.y);
                *(__half2*)(h + (size_t)gm * OUTC + gc) = o;
            }
            if (gm + 8 < NNODES) {
                __half2 o = __floats2half2_rn(acc[mt][nt][2] + bias.x,
                                              acc[mt][nt][3] + bias.y);
                *(__half2*)(h + (size_t)(gm + 8) * OUTC + gc) = o;
            }
        }
    }
}

// ---------------------------------------------------------------------------
// Phase 1: histogram  seg = hop*NNODES + row
// ---------------------------------------------------------------------------
__global__ void sign_hist_kernel(const int* __restrict__ rows)
{
    int e   = blockIdx.x * blockDim.x + threadIdx.x;
    int hop = blockIdx.y;
    if (e >= NEDGES) return;
    int r = rows[hop * NEDGES + e];
    atomicAdd(&g_counts[hop * NNODES + r], 1);
}

// Phase 2a: per-block (2048-chunk) reduction of counts
__global__ __launch_bounds__(256) void sign_scan_reduce_kernel(void)
{
    __shared__ int ssum[256];
    int base = blockIdx.x * SCAN_CHUNK;
    int t = threadIdx.x;
    int s = 0;
    #pragma unroll
    for (int j = 0; j < 8; j++) {
        int idx = base + t * 8 + j;
        if (idx < NSEG) s += g_counts[idx];
    }
    ssum[t] = s;
    __syncthreads();
    for (int off = 128; off; off >>= 1) {
        if (t < off) ssum[t] += ssum[t + off];
        __syncthreads();
    }
    if (t == 0) g_blksum[blockIdx.x] = ssum[0];
}

// Phase 2b: exclusive scan of block sums (tiny, serial)
__global__ void sign_scan_blks_kernel(void)
{
    if (threadIdx.x == 0 && blockIdx.x == 0) {
        int acc = 0;
        for (int i = 0; i < NSCANBLK; i++) {
            int v = g_blksum[i];
            g_blkoff[i] = acc;
            acc += v;
        }
    }
}

// Phase 2c: final exclusive scan within each chunk; writes offsets + head
__global__ __launch_bounds__(256) void sign_scan_final_kernel(void)
{
    __shared__ int wsum[8];
    int base = blockIdx.x * SCAN_CHUNK;
    int t = threadIdx.x;
    int lane = t & 31, w = t >> 5;

    int v[8];
    int s = 0;
    #pragma unroll
    for (int j = 0; j < 8; j++) {
        int idx = base + t * 8 + j;
        v[j] = (idx < NSEG) ? g_counts[idx] : 0;
        s += v[j];
    }
    int incl = s;
    #pragma unroll
    for (int off = 1; off < 32; off <<= 1) {
        int n = __shfl_up_sync(0xFFFFFFFFu, incl, off);
        if (lane >= off) incl += n;
    }
    if (lane == 31) wsum[w] = incl;
    __syncthreads();
    if (w == 0 && lane < 8) {
        int ws = wsum[lane];
        int wincl = ws;
        #pragma unroll
        for (int off = 1; off < 8; off <<= 1) {
            int n = __shfl_up_sync(0xFFu, wincl, off);
            if (lane >= off) wincl += n;
        }
        wsum[lane] = wincl - ws;
    }
    __syncthreads();

    int run = (incl - s) + wsum[w] + g_blkoff[blockIdx.x];
    #pragma unroll
    for (int j = 0; j < 8; j++) {
        int idx = base + t * 8 + j;
        if (idx < NSEG) {
            g_offsets[idx] = run;
            g_head[idx]    = run;
        }
        run += v[j];
    }
}

// Phase 3: fill sorted edge list (packed col + val bits)
__global__ void sign_fill_kernel(const int* __restrict__ rows,
                                 const int* __restrict__ cols,
                                 const float* __restrict__ vals)
{
    int e   = blockIdx.x * blockDim.x + threadIdx.x;
    int hop = blockIdx.y;
    if (e >= NEDGES) return;
    int idx = hop * NEDGES + e;
    int r = rows[idx];
    int pos = atomicAdd(&g_head[hop * NNODES + r], 1);
    g_sorted[pos] = make_uint2((uint32_t)cols[idx], __float_as_uint(vals[idx]));
}

// Phase 4: segment accumulate + ELU (R10 form) over segments
// [seg0, seg0+segN). Launched twice: hops {0,1} then hops {2,3}.
__global__ __launch_bounds__(256) void sign_accum_kernel(
    float* __restrict__ out, int seg0, int segN)
{
    const int wid  = threadIdx.x >> 5;
    const int lane = threadIdx.x & 31;
    const int seg  = seg0 + blockIdx.x * 8 + wid;
    if (seg >= seg0 + segN) return;

    const int hop = seg / NNODES;
    const int row = seg - hop * NNODES;
    const int start = g_offsets[seg];
    const int end   = (seg == NSEG - 1) ? TOTE : g_offsets[seg + 1];
    const int coloff = hop * NHID + lane * 2;

    float ax = 0.f, ay = 0.f;
    int i = start;
    for (; i + 1 < end; i += 2) {
        uint2 cv0 = g_sorted[i];
        uint2 cv1 = g_sorted[i + 1];
        __half2 h0 = *(const __half2*)(g_h + (size_t)cv0.x * OUTC + coloff);
        __half2 h1 = *(const __half2*)(g_h + (size_t)cv1.x * OUTC + coloff);
        float v0 = __uint_as_float(cv0.y);
        float v1 = __uint_as_float(cv1.y);
        float2 f0 = __half22float2(h0);
        float2 f1 = __half22float2(h1);
        ax += v0 * f0.x; ay += v0 * f0.y;
        ax += v1 * f1.x; ay += v1 * f1.y;
    }
    if (i < end) {
        uint2 cv = g_sorted[i];
        __half2 hh = *(const __half2*)(g_h + (size_t)cv.x * OUTC + coloff);
        float v = __uint_as_float(cv.y);
        float2 f = __half22float2(hh);
        ax += v * f.x; ay += v * f.y;
    }

    ax = (ax > 0.f) ? ax : expm1f(ax);
    ay = (ay > 0.f) ? ay : expm1f(ay);
    float2 o; o.x = ax; o.y = ay;
    *(float2*)(out + (size_t)row * OUTC + coloff) = o;
}

// ---------------------------------------------------------------------------
// Launcher: 3-branch pipelined capture.
//   s0:    xconv -> wconv -> gemm(cg0) -e_g0-> gemm(cg1) ... wait(e_a01) -> accum23
//   side:  zero -> hist -> scans -> fill -e_fill
//   s_acc: wait(e_g0), wait(e_fill) -> accum01 -e_a01
// accum01 (mem-latency bound, smem-free) co-resides with gemm(cg1)
// (tensor-issue bound, 1 CTA/SM). Disjoint data: reads h cols 0-127,
// gemm(cg1) writes cols 128-255.
// ---------------------------------------------------------------------------
extern "C" void kernel_launch(void* const* d_in, const int* in_sizes, int n_in,
                              void* d_out, int out_size)
{
    const float* x    = (const float*)d_in[0];
    const float* W    = (const float*)d_in[1];
    const float* b    = (const float*)d_in[2];
    const int*   rows = (const int*)  d_in[3];
    const int*   cols = (const int*)  d_in[4];
    const float* vals = (const float*)d_in[5];
    float* out = (float*)d_out;

    __half* h;
    cudaGetSymbolAddress((void**)&h, g_h);

    static cudaStream_t s_side = nullptr, s_acc = nullptr;
    static cudaEvent_t  e_fork = nullptr, e_fill = nullptr,
                        e_g0 = nullptr, e_a01 = nullptr;
    if (s_side == nullptr) {
        cudaStreamCreateWithFlags(&s_side, cudaStreamNonBlocking);
        cudaStreamCreateWithFlags(&s_acc,  cudaStreamNonBlocking);
        cudaEventCreateWithFlags(&e_fork, cudaEventDisableTiming);
        cudaEventCreateWithFlags(&e_fill, cudaEventDisableTiming);
        cudaEventCreateWithFlags(&e_g0,   cudaEventDisableTiming);
        cudaEventCreateWithFlags(&e_a01,  cudaEventDisableTiming);
        cudaFuncSetAttribute(sign_gemm_mma_kernel,
                             cudaFuncAttributeMaxDynamicSharedMemorySize, SM_TOTAL);
    }

    const int HALF_SEGS = 2 * NNODES;                 // segments per 2 hops
    const int ACC_BLKS  = (HALF_SEGS + 7) / 8;        // 12500

    // fork
    cudaEventRecord(e_fork, 0);
    cudaStreamWaitEvent(s_side, e_fork, 0);
    cudaStreamWaitEvent(s_acc,  e_fork, 0);

    // ---- side chain: bucketing prep ----
    sign_zero_counts_kernel<<<(NSEG + 255) / 256, 256, 0, s_side>>>();
    dim3 egrid((NEDGES + 255) / 256, HOPS);
    sign_hist_kernel<<<egrid, 256, 0, s_side>>>(rows);
    sign_scan_reduce_kernel<<<NSCANBLK, 256, 0, s_side>>>();
    sign_scan_blks_kernel<<<1, 32, 0, s_side>>>();
    sign_scan_final_kernel<<<NSCANBLK, 256, 0, s_side>>>();
    sign_fill_kernel<<<egrid, 256, 0, s_side>>>(rows, cols, vals);
    cudaEventRecord(e_fill, s_side);

    // ---- main chain: conversions + gemm cg0 ----
    sign_xconv_kernel<<<(NNODES * NFEAT / 4 + 255) / 256, 256>>>(x);
    sign_wconv_kernel<<<(WCONV_ELEMS + 255) / 256, 256>>>(W);
    dim3 ggrid((NNODES + 127) / 128);
    sign_gemm_mma_kernel<<<ggrid, 256, SM_TOTAL>>>(b, h, 0);
    cudaEventRecord(e_g0, 0);

    // ---- gemm cg1 (s0) overlapped with accum hops 0-1 (s_acc) ----
    sign_gemm_mma_kernel<<<ggrid, 256, SM_TOTAL>>>(b, h, 1);

    cudaStreamWaitEvent(s_acc, e_g0, 0);
    cudaStreamWaitEvent(s_acc, e_fill, 0);
    sign_accum_kernel<<<ACC_BLKS, 256, 0, s_acc>>>(out, 0, HALF_SEGS);
    cudaEventRecord(e_a01, s_acc);

    // ---- join + accum hops 2-3 ----
    cudaStreamWaitEvent(0, e_a01, 0);
    sign_accum_kernel<<<ACC_BLKS, 256>>>(out, HALF_SEGS, HALF_SEGS);
}